// round 6
// baseline (speedup 1.0000x reference)
#include <cuda_runtime.h>

// Single-kernel ball query, direct-binned 12^3 grid.
// N1=4096 queries, N2=16384 refs, K=32, r=0.08, points uniform [0,1)^3.
//
// R6 vs R5:
//  - 128 blocks x 1024 threads, launch_bounds(1024,1): 1 block/SM, balanced
//    phases (zero: 14 cells/block, build: 128 points/block, query: 32
//    queries/block) -> no straggler block at either barrier.
//  - Arrive/release-split grid barrier: waiters poll a separate monotone
//    release word, never the atomically-hammered arrival counter.
//  - Hit records packed to one int (idx<<17 | cell_slot_addr): 16KB smem,
//    epilogue reloads the point from L1-hot g_cp.
//
// Replay-safe: g_arrive/g_release monotone (no reset); g_n re-zeroed at
// phase 0 each call (.bss zero on first call). Output deterministic: hits
// ranked by unique original index, append order never reaches the output.
//
// Hit predicate bit-identical to verified formula (rel_err 0.0 x5):
//   s = ((x*x + y*y) + z*z)  (mul/add, no fma contraction)
//   dot = fmaf(z1,z2, fmaf(y1,y2, x1*x2))
//   d2  = (s1 + s2) - 2*dot;  hit iff d2 <= r^2

#define BQ_N1 4096
#define BQ_N2 16384
#define BQ_K 32
#define BQ_R2 0.0064f
#define BQ_R2P 0.00641f
#define BQ_G 12
#define BQ_NC (BQ_G * BQ_G * BQ_G)  // 1728
#define BQ_CAP 48                   // per-cell capacity, bounds-guarded
#define BQ_BUF 128
#define NBLK 128
#define NTHR 1024
#define NWARP 32
#define ZPB 14                      // cells zeroed per block (128*14 >= 1728)
#define PPB 128                     // points binned per block (128*128 = 16384)

__device__ unsigned g_arrive;           // monotone arrival tickets
__device__ unsigned g_release;          // monotone completed-generation count
__device__ int g_n[BQ_NC];              // per-cell counts (zero at entry)
__device__ float4 g_cp[BQ_NC * BQ_CAP]; // x, y, z, idx_bits

__device__ __forceinline__ int cell1(float v) {
    int c = (int)(v * (float)BQ_G);
    return c < 0 ? 0 : (c > BQ_G - 1 ? BQ_G - 1 : c);
}

// Grid barrier, arrive/release split. All 128 blocks co-resident
// (launch_bounds(1024,1), 128 <= 148 SMs) -> spin is deadlock-free.
__device__ __forceinline__ void gbar() {
    __syncthreads();
    __threadfence();  // release: publish this thread's writes (flushes L1D)
    if (threadIdx.x == 0) {
        unsigned my = atomicAdd(&g_arrive, 1u);
        unsigned target = my / NBLK + 1u;
        if (my % NBLK == NBLK - 1u) {
            atomicAdd(&g_release, 1u);  // last arriver releases generation
        } else {
            while (*(volatile unsigned*)&g_release < target) __nanosleep(20);
        }
    }
    __syncthreads();
    __threadfence();  // acquire: post-barrier loads see remote writes
}

__global__ __launch_bounds__(NTHR, 1) void bq_all(const float* __restrict__ p1,
                                                  const float* __restrict__ p2,
                                                  float* __restrict__ out) {
    __shared__ int sh_key[NWARP][BQ_BUF];  // 16 KB packed hit records
    __shared__ int s_wcnt[NWARP];

    int tid = threadIdx.x;
    int warp = tid >> 5;
    int lane = tid & 31;
    int q = blockIdx.x * NWARP + warp;     // exactly 4096 queries

    // ---- Phase 0: zero counters (balanced) + load query point ----
    if (tid < ZPB) {
        int c = blockIdx.x * ZPB + tid;
        if (c < BQ_NC) g_n[c] = 0;
    }
    if (tid < NWARP) s_wcnt[tid] = 0;
    float x1 = p1[3 * q + 0];
    float y1 = p1[3 * q + 1];
    float z1 = p1[3 * q + 2];
    gbar();

    // ---- Phase 1: build, 128 points per block (all SMs busy) ----
    if (tid < PPB) {
        int j = blockIdx.x * PPB + tid;
        float px = p2[3 * j + 0];
        float py = p2[3 * j + 1];
        float pz = p2[3 * j + 2];
        int c = (cell1(pz) * BQ_G + cell1(py)) * BQ_G + cell1(px);
        int slot = atomicAdd(&g_n[c], 1);
        if (slot < BQ_CAP)
            g_cp[c * BQ_CAP + slot] =
                make_float4(px, py, pz, __int_as_float(j));
    }
    gbar();

    // ---- Phase 2: query (one warp per query) ----
    float s1 = __fadd_rn(__fadd_rn(__fmul_rn(x1, x1), __fmul_rn(y1, y1)),
                         __fmul_rn(z1, z1));
    int cx = cell1(x1), cy = cell1(y1), cz = cell1(z1);
    int xlo = cx > 0 ? cx - 1 : 0;
    int xhi = cx < BQ_G - 1 ? cx + 1 : BQ_G - 1;

    const float invG = 1.0f / (float)BQ_G;
    float dxl = x1 - (float)cx * invG, dxr = (float)(cx + 1) * invG - x1;
    float dyl = y1 - (float)cy * invG, dyr = (float)(cy + 1) * invG - y1;
    float dzl = z1 - (float)cz * invG, dzr = (float)(cz + 1) * invG - z1;
    float dxl2 = dxl * dxl, dxr2 = dxr * dxr;

    int* keyb = sh_key[warp];
    int* wcnt = &s_wcnt[warp];

    #pragma unroll
    for (int dz = -1; dz <= 1; dz++) {
        int zz = cz + dz;
        if (zz < 0 || zz >= BQ_G) continue;
        float ddz = (dz < 0) ? dzl : ((dz > 0) ? dzr : 0.0f);
        float dz2 = ddz * ddz;
        #pragma unroll
        for (int dy = -1; dy <= 1; dy++) {
            int yy = cy + dy;
            if (yy < 0 || yy >= BQ_G) continue;
            float ddy = (dy < 0) ? dyl : ((dy > 0) ? dyr : 0.0f);
            float dyz2 = dz2 + ddy * ddy;
            if (dyz2 > BQ_R2P) continue;                   // row unreachable
            int xl = xlo, xh = xhi;
            if (xl < cx && dxl2 + dyz2 > BQ_R2P) xl = cx;  // left cell out
            if (xh > cx && dxr2 + dyz2 > BQ_R2P) xh = cx;  // right cell out
            int c0 = (zz * BQ_G + yy) * BQ_G + xl;
            int ncell = xh - xl + 1;
            int n0 = min(g_n[c0], BQ_CAP);
            int n1 = (ncell > 1) ? min(g_n[c0 + 1], BQ_CAP) : 0;
            int n2 = (ncell > 2) ? min(g_n[c0 + 2], BQ_CAP) : 0;
            int t01 = n0 + n1;
            int tot = t01 + n2;
            int base0 = c0 * BQ_CAP;
            for (int t = lane; t < tot; t += 32) {
                int addr;
                if (t < n0)       addr = base0 + t;
                else if (t < t01) addr = base0 + BQ_CAP + (t - n0);
                else              addr = base0 + 2 * BQ_CAP + (t - t01);
                float4 p = g_cp[addr];
                float s2 = __fadd_rn(
                    __fadd_rn(__fmul_rn(p.x, p.x), __fmul_rn(p.y, p.y)),
                    __fmul_rn(p.z, p.z));
                float dot = fmaf(z1, p.z, fmaf(y1, p.y, __fmul_rn(x1, p.x)));
                float d2 = __fsub_rn(__fadd_rn(s1, s2), __fmul_rn(2.0f, dot));
                if (d2 <= BQ_R2) {
                    int pos = atomicAdd(wcnt, 1);
                    if (pos < BQ_BUF)
                        keyb[pos] = (__float_as_int(p.w) << 17) | addr;
                }
            }
        }
    }
    __syncwarp();
    int cnt = *wcnt;
    __syncwarp();

    float* mapping = out + (size_t)q * BQ_K;
    float* num_out = out + (size_t)BQ_N1 * BQ_K + q;
    float* coords  = out + (size_t)BQ_N1 * BQ_K + BQ_N1 + (size_t)q * BQ_K * 3;

    int cc = cnt < BQ_BUF ? cnt : BQ_BUF;
    // Rank by packed key (idx-major, idx unique) -> reference's "first K in
    // ascending original index" order, independent of append order.
    for (int e0 = lane; e0 < cc; e0 += 32) {
        int key = keyb[e0];
        int rank = 0;
        for (int i = 0; i < cc; i++) rank += (keyb[i] < key);
        if (rank < BQ_K) {
            float4 p = g_cp[key & 0x1FFFF];  // L1-hot reload
            mapping[rank] = (float)(key >> 17);
            coords[rank * 3 + 0] = p.x;
            coords[rank * 3 + 1] = p.y;
            coords[rank * 3 + 2] = p.z;
        }
    }

    int n = cnt < BQ_K ? cnt : BQ_K;
    if (lane == 0) *num_out = (float)n;
    for (int s = n + lane; s < BQ_K; s += 32) {
        mapping[s] = 0.0f;
        coords[s * 3 + 0] = 0.0f;
        coords[s * 3 + 1] = 0.0f;
        coords[s * 3 + 2] = 0.0f;
    }
}

extern "C" void kernel_launch(void* const* d_in, const int* in_sizes, int n_in,
                              void* d_out, int out_size) {
    const float* p1 = (const float*)d_in[0];
    const float* p2 = (const float*)d_in[1];
    float* out = (float*)d_out;
    bq_all<<<NBLK, NTHR>>>(p1, p2, out);
}